// round 1
// baseline (speedup 1.0000x reference)
#include <cuda_runtime.h>
#include <math.h>

#define BB  8
#define NN1 128
#define NN2 512
#define DD  128

// ---------------- static device scratch (no runtime allocation) ----------------
__device__ float g_g1 [BB*NN1*DD];
__device__ float g_g2 [BB*NN2*DD];
__device__ float g_h  [BB*NN2*DD];
__device__ float g_hA [BB*NN2*DD];
__device__ float g_e  [BB*NN2*NN2];
__device__ float g_att[BB*NN2*NN2];
__device__ float g_hp [BB*NN2*DD];
__device__ float g_P1A[BB*NN1*DD];
__device__ float g_P1B[BB*NN1*DD];
__device__ float g_P2A[BB*NN2*DD];
__device__ float g_P2B[BB*NN2*DD];
__device__ float g_part[BB*NN1*4];

// ---------------- kernels ----------------

// Y[bn, d] = sum_l X[bn, l] * W[l, d], L = 54
__global__ void k_embed(const float* __restrict__ X, const float* __restrict__ W,
                        float* __restrict__ Y) {
    int bn = blockIdx.x;
    __shared__ float xs[54];
    if (threadIdx.x < 54) xs[threadIdx.x] = X[(size_t)bn*54 + threadIdx.x];
    __syncthreads();
    int d = threadIdx.x;
    float acc = 0.f;
    #pragma unroll
    for (int l = 0; l < 54; l++) acc += xs[l] * W[l*DD + d];
    Y[(size_t)bn*DD + d] = acc;
}

// Y[bn, d] = bias[d] + sum_l X[bn, l] * W[l, d], L = D = 128
__global__ void k_linear(const float* __restrict__ X, const float* __restrict__ W,
                         const float* __restrict__ bias, float* __restrict__ Y) {
    int bn = blockIdx.x;
    __shared__ float xs[DD];
    xs[threadIdx.x] = X[(size_t)bn*DD + threadIdx.x];
    __syncthreads();
    int d = threadIdx.x;
    float acc = bias ? bias[d] : 0.f;
    #pragma unroll 8
    for (int l = 0; l < DD; l++) acc += xs[l] * W[l*DD + d];
    Y[(size_t)bn*DD + d] = acc;
}

// C[b,i,k] = sum_d A[b,i,d] * Bm[b,k,d]   (A, Bm: [B,N,D] row-major; C: [B,N,N])
// 32x32 output tile, 16x16 threads, 2x2 micro-tile.
__global__ void k_ABt(const float* __restrict__ A, const float* __restrict__ Bm,
                      float* __restrict__ C, int N) {
    __shared__ float As[32][33];
    __shared__ float Bs[32][33];
    int b = blockIdx.z;
    int i0 = blockIdx.y * 32, k0 = blockIdx.x * 32;
    const float* Ab = A + (size_t)b*N*DD;
    const float* Bb = Bm + (size_t)b*N*DD;
    int tx = threadIdx.x, ty = threadIdx.y;
    int tid = ty*16 + tx;
    int lr = tid >> 3;           // 0..31
    int lc = (tid & 7) * 4;      // 0,4,...,28
    float acc00 = 0.f, acc01 = 0.f, acc10 = 0.f, acc11 = 0.f;
    for (int d0 = 0; d0 < DD; d0 += 32) {
        float4 a4 = *reinterpret_cast<const float4*>(&Ab[(size_t)(i0+lr)*DD + d0 + lc]);
        As[lr][lc] = a4.x; As[lr][lc+1] = a4.y; As[lr][lc+2] = a4.z; As[lr][lc+3] = a4.w;
        float4 b4 = *reinterpret_cast<const float4*>(&Bb[(size_t)(k0+lr)*DD + d0 + lc]);
        Bs[lr][lc] = b4.x; Bs[lr][lc+1] = b4.y; Bs[lr][lc+2] = b4.z; Bs[lr][lc+3] = b4.w;
        __syncthreads();
        #pragma unroll
        for (int d = 0; d < 32; d++) {
            float a0 = As[ty][d], a1 = As[ty+16][d];
            float bb0 = Bs[tx][d], bb1 = Bs[tx+16][d];
            acc00 += a0*bb0; acc01 += a0*bb1; acc10 += a1*bb0; acc11 += a1*bb1;
        }
        __syncthreads();
    }
    float* Cb = C + (size_t)b*N*N;
    Cb[(size_t)(i0+ty   )*N + k0+tx   ] = acc00;
    Cb[(size_t)(i0+ty   )*N + k0+tx+16] = acc01;
    Cb[(size_t)(i0+ty+16)*N + k0+tx   ] = acc10;
    Cb[(size_t)(i0+ty+16)*N + k0+tx+16] = acc11;
}

// L[b,i,k] = adj>0 ? E[b,i,k] + E[b,k,i] : -9e15
__global__ void k_masksym(const float* __restrict__ E, const float* __restrict__ adj,
                          float* __restrict__ L, int N) {
    int idx = blockIdx.x * blockDim.x + threadIdx.x;
    int NN = N * N;
    int b = idx / NN;
    int r = idx - b * NN;
    int i = r / N;
    int k = r - i * N;
    float a = adj[idx];
    size_t base = (size_t)b * NN;
    float v = (a > 0.f) ? (E[base + (size_t)i*N + k] + E[base + (size_t)k*N + i]) : -9e15f;
    L[idx] = v;
}

// Column softmax over i (axis=1), then multiply by adj. In-place on L.
// block (32,8): x = column k within tile (coalesced), y = i-chunk
__global__ void k_softmax(float* __restrict__ L, const float* __restrict__ adj, int N) {
    int b = blockIdx.y;
    int k = blockIdx.x * 32 + threadIdx.x;
    int ty = threadIdx.y;
    float* Lb = L + (size_t)b*N*N;
    const float* Ab = adj + (size_t)b*N*N;
    __shared__ float red[8][33];
    float m = -3.4e38f;
    for (int i = ty; i < N; i += 8) m = fmaxf(m, Lb[(size_t)i*N + k]);
    red[ty][threadIdx.x] = m;
    __syncthreads();
    if (ty == 0) {
        float mm = red[0][threadIdx.x];
        #pragma unroll
        for (int y = 1; y < 8; y++) mm = fmaxf(mm, red[y][threadIdx.x]);
        red[0][threadIdx.x] = mm;
    }
    __syncthreads();
    m = red[0][threadIdx.x];
    __syncthreads();
    float s = 0.f;
    for (int i = ty; i < N; i += 8) {
        float e = __expf(Lb[(size_t)i*N + k] - m);
        Lb[(size_t)i*N + k] = e;
        s += e;
    }
    red[ty][threadIdx.x] = s;
    __syncthreads();
    if (ty == 0) {
        float ss = 0.f;
        #pragma unroll
        for (int y = 0; y < 8; y++) ss += red[y][threadIdx.x];
        red[0][threadIdx.x] = ss;
    }
    __syncthreads();
    float inv = 1.f / red[0][threadIdx.x];
    for (int i = ty; i < N; i += 8) {
        size_t o = (size_t)i*N + k;
        Lb[o] = Lb[o] * inv * Ab[o];
    }
}

// C[b,i,d] = relu( sum_j A[b,i,j] * Bm[b,j,d] )   A:[B,N,N], Bm:[B,N,D]
__global__ void k_AB_relu(const float* __restrict__ A, const float* __restrict__ Bm,
                          float* __restrict__ C, int N) {
    __shared__ float As[32][33];
    __shared__ float Bs[32][33];
    int b = blockIdx.z;
    int i0 = blockIdx.y * 32, d0 = blockIdx.x * 32;
    const float* Ab = A + (size_t)b*N*N;
    const float* Bb = Bm + (size_t)b*N*DD;
    int tx = threadIdx.x, ty = threadIdx.y;
    int tid = ty*16 + tx;
    int lr = tid >> 3;
    int lc = (tid & 7) * 4;
    float acc00 = 0.f, acc01 = 0.f, acc10 = 0.f, acc11 = 0.f;
    for (int j0 = 0; j0 < N; j0 += 32) {
        float4 a4 = *reinterpret_cast<const float4*>(&Ab[(size_t)(i0+lr)*N + j0 + lc]);
        As[lr][lc] = a4.x; As[lr][lc+1] = a4.y; As[lr][lc+2] = a4.z; As[lr][lc+3] = a4.w;
        float4 b4 = *reinterpret_cast<const float4*>(&Bb[(size_t)(j0+lr)*DD + d0 + lc]);
        Bs[lr][lc] = b4.x; Bs[lr][lc+1] = b4.y; Bs[lr][lc+2] = b4.z; Bs[lr][lc+3] = b4.w;
        __syncthreads();
        #pragma unroll
        for (int j = 0; j < 32; j++) {
            float a0 = As[ty][j], a1 = As[ty+16][j];
            float bb0 = Bs[j][tx], bb1 = Bs[j][tx+16];
            acc00 += a0*bb0; acc01 += a0*bb1; acc10 += a1*bb0; acc11 += a1*bb1;
        }
        __syncthreads();
    }
    float* Cb = C + (size_t)b*N*DD;
    Cb[(size_t)(i0+ty   )*DD + d0+tx   ] = fmaxf(acc00, 0.f);
    Cb[(size_t)(i0+ty   )*DD + d0+tx+16] = fmaxf(acc01, 0.f);
    Cb[(size_t)(i0+ty+16)*DD + d0+tx   ] = fmaxf(acc10, 0.f);
    Cb[(size_t)(i0+ty+16)*DD + d0+tx+16] = fmaxf(acc11, 0.f);
}

// gated residual: coeff = sigmoid(x.gW[:D] + hp.gW[D:] + gb); g = c*x + (1-c)*hp
__global__ void k_gate(float* __restrict__ g, const float* __restrict__ hp,
                       const float* __restrict__ gW, const float* __restrict__ gb) {
    int bn = blockIdx.x, t = threadIdx.x;
    size_t base = (size_t)bn*DD;
    float x = g[base + t], h = hp[base + t];
    float v = x * gW[t] + h * gW[DD + t];
    #pragma unroll
    for (int o = 16; o > 0; o >>= 1) v += __shfl_down_sync(0xffffffffu, v, o);
    __shared__ float red[4];
    __shared__ float csh;
    if ((t & 31) == 0) red[t >> 5] = v;
    __syncthreads();
    if (t == 0) {
        float s = red[0] + red[1] + red[2] + red[3] + gb[0];
        csh = 1.f / (1.f + __expf(-s));
    }
    __syncthreads();
    float c = csh;
    g[base + t] = c * x + (1.f - c) * h;
}

// per-(b,i): loop all j, compute both pair MLPs + physics, partial sums -> g_part
__global__ void k_pair(const float* __restrict__ P1A, const float* __restrict__ P1B,
                       const float* __restrict__ P2A, const float* __restrict__ P2B,
                       const float* __restrict__ w2A, const float* __restrict__ w2B,
                       const float* __restrict__ b2A, const float* __restrict__ b2B,
                       const float* __restrict__ pos1, const float* __restrict__ pos2,
                       const float* __restrict__ r1, const float* __restrict__ r2,
                       const float* __restrict__ nm1, const float* __restrict__ nm2,
                       const float* __restrict__ A_int, float* __restrict__ part) {
    int b = blockIdx.x >> 7;
    int i = blockIdx.x & 127;
    int t = threadIdx.x, lane = t & 31, w = t >> 5;
    __shared__ float p1a[DD], p1b[DD], w2a[DD], w2b[DD];
    size_t rbase = ((size_t)b*NN1 + i)*DD;
    p1a[t] = P1A[rbase + t];
    p1b[t] = P1B[rbase + t];
    w2a[t] = w2A[t];
    w2b[t] = w2B[t];
    __syncthreads();
    float px = pos1[(b*NN1 + i)*3 + 0];
    float py = pos1[(b*NN1 + i)*3 + 1];
    float pz = pos1[(b*NN1 + i)*3 + 2];
    float rr1 = r1[b*NN1 + i];
    float m1  = nm1[b*NN1 + i];
    float b2a = b2A[0], b2b = b2B[0];
    size_t a_base = (size_t)b*8*NN1*NN2 + (size_t)i*NN2;
    const size_t chw = (size_t)NN1*NN2;
    float s0 = 0.f, s1 = 0.f, s2 = 0.f, s3 = 0.f;
    for (int j = w; j < NN2; j += 4) {
        const float* p2a = P2A + ((size_t)b*NN2 + j)*DD;
        const float* p2b = P2B + ((size_t)b*NN2 + j)*DD;
        float za = 0.f, zb = 0.f;
        #pragma unroll
        for (int hh = 0; hh < 4; hh++) {
            int h = lane + hh*32;
            za += fmaxf(p1a[h] + p2a[h], 0.f) * w2a[h];
            zb += fmaxf(p1b[h] + p2b[h], 0.f) * w2b[h];
        }
        #pragma unroll
        for (int o = 16; o > 0; o >>= 1) {
            za += __shfl_down_sync(0xffffffffu, za, o);
            zb += __shfl_down_sync(0xffffffffu, zb, o);
        }
        if (lane == 0) {
            za += b2a; zb += b2b;
            float Aw = 1.f / (1.f + __expf(-za));
            float Bw = tanhf(zb) * 0.2f;
            float dx = px - pos2[(b*NN2 + j)*3 + 0];
            float dy = py - pos2[(b*NN2 + j)*3 + 1];
            float dz = pz - pos2[(b*NN2 + j)*3 + 2];
            float dm = sqrtf(dx*dx + dy*dy + dz*dz + 1e-10f);
            if (dm < 0.5f) dm = 1e10f;
            float dm0 = rr1 + r2[b*NN2 + j] + Bw;
            float dm0s = (dm0 < 1e-4f) ? 1.f : dm0;
            float rq = dm0s / dm;
            float rq2 = rq*rq;
            float r6 = rq2*rq2*rq2;
            float evdw = fminf(r6*r6 - 2.f*r6, 100.f);
            float Aamp = Aw * (0.0356f - 0.0178f) + 0.0178f;
            s0 += Aamp * evdw * m1 * nm2[b*NN2 + j];
            float dmd = dm - dm0;
            float a1 = A_int[a_base + 1*chw + j];
            float a7 = A_int[a_base + 7*chw + j];
            float a6 = A_int[a_base + 6*chw + j];
            s1 += fminf(fmaxf(dmd * a1 * (-1.f/0.7f), 0.f), 1.f);
            s2 += fminf(fmaxf(dmd * a7 * (-1.f/0.7f), 0.f), 1.f);
            s3 += fminf(fmaxf((1.5f - dmd) * a6, 0.f), 1.f);
        }
    }
    __shared__ float acc[4][4];
    if (lane == 0) { acc[w][0] = s0; acc[w][1] = s1; acc[w][2] = s2; acc[w][3] = s3; }
    __syncthreads();
    if (t < 4) {
        part[((size_t)b*NN1 + i)*4 + t] = acc[0][t] + acc[1][t] + acc[2][t] + acc[3][t];
    }
}

__global__ void k_final(const float* __restrict__ part, const float* __restrict__ rotor,
                        const float* __restrict__ duff, const float* __restrict__ hbc,
                        const float* __restrict__ hyc, const float* __restrict__ vdc,
                        const float* __restrict__ rtc, float* __restrict__ out) {
    int b = blockIdx.x, t = threadIdx.x;
    size_t base = ((size_t)b*NN1 + t)*4;
    float v0 = part[base+0], v1 = part[base+1], v2 = part[base+2], v3 = part[base+3];
    #pragma unroll
    for (int o = 16; o > 0; o >>= 1) {
        v0 += __shfl_down_sync(0xffffffffu, v0, o);
        v1 += __shfl_down_sync(0xffffffffu, v1, o);
        v2 += __shfl_down_sync(0xffffffffu, v2, o);
        v3 += __shfl_down_sync(0xffffffffu, v3, o);
    }
    __shared__ float red[4][4];
    if ((t & 31) == 0) {
        int w = t >> 5;
        red[w][0] = v0; red[w][1] = v1; red[w][2] = v2; red[w][3] = v3;
    }
    __syncthreads();
    if (t == 0) {
        float s0 = red[0][0]+red[1][0]+red[2][0]+red[3][0];
        float s1 = red[0][1]+red[1][1]+red[2][1]+red[3][1];
        float s2 = red[0][2]+red[1][2]+red[2][2]+red[3][2];
        float s3 = red[0][3]+red[1][3]+red[2][3]+red[3][3];
        float hb = -hbc[0]*hbc[0];
        float hy = -hyc[0]*hyc[0];
        float inv = 1.f / (1.f + rtc[0]*rtc[0]*rotor[b]);
        out[b*5+0] = s0 * inv;
        out[b*5+1] = s1 * hb * inv;
        out[b*5+2] = s2 * hb * inv;
        out[b*5+3] = s3 * hy * inv;
        out[b*5+4] = duff[b]*vdc[0]*vdc[0]*inv;
    }
}

// ---------------- host side ----------------

static void run_gat_layer(float* g, const float* adj, int N, int layer,
                          const float* gat_W, const float* gat_b, const float* gat_A,
                          const float* gate_W, const float* gate_b,
                          float* hbuf, float* hAbuf, float* ebuf, float* attbuf, float* hpbuf) {
    int BN = BB * N;
    k_linear<<<BN, 128>>>(g, gat_W + (size_t)layer*DD*DD, gat_b + layer*DD, hbuf);
    k_linear<<<BN, 128>>>(hbuf, gat_A + (size_t)layer*DD*DD, nullptr, hAbuf);
    k_ABt<<<dim3(N/32, N/32, BB), dim3(16,16)>>>(hAbuf, hbuf, ebuf, N);
    int tot = BB * N * N;
    k_masksym<<<tot/256, 256>>>(ebuf, adj, attbuf, N);
    k_softmax<<<dim3(N/32, BB), dim3(32,8)>>>(attbuf, adj, N);
    k_AB_relu<<<dim3(DD/32, N/32, BB), dim3(16,16)>>>(attbuf, hbuf, hpbuf, N);
    k_gate<<<BN, 128>>>(g, hpbuf, gate_W + (size_t)layer*2*DD, gate_b + layer);
}

extern "C" void kernel_launch(void* const* d_in, const int* in_sizes, int n_in,
                              void* d_out, int out_size) {
    (void)in_sizes; (void)n_in; (void)out_size;
    const float* h1       = (const float*)d_in[0];
    const float* adj1     = (const float*)d_in[1];
    const float* h2       = (const float*)d_in[2];
    const float* adj2     = (const float*)d_in[3];
    const float* A_int    = (const float*)d_in[4];
    const float* pos1     = (const float*)d_in[5];
    const float* pos2     = (const float*)d_in[6];
    const float* rotor    = (const float*)d_in[7];
    const float* vdw_r1   = (const float*)d_in[8];
    const float* vdw_r2   = (const float*)d_in[9];
    const float* duff     = (const float*)d_in[10];
    const float* nm1      = (const float*)d_in[11];
    const float* nm2      = (const float*)d_in[12];
    const float* node_W   = (const float*)d_in[13];
    const float* gat_W    = (const float*)d_in[14];
    const float* gat_b    = (const float*)d_in[15];
    const float* gat_A    = (const float*)d_in[16];
    const float* gate_W   = (const float*)d_in[17];
    const float* gate_b   = (const float*)d_in[18];
    const float* vdwA_W1  = (const float*)d_in[19];
    const float* vdwA_b1  = (const float*)d_in[20];
    const float* vdwA_W2  = (const float*)d_in[21];
    const float* vdwA_b2  = (const float*)d_in[22];
    const float* vdwB_W1  = (const float*)d_in[23];
    const float* vdwB_b1  = (const float*)d_in[24];
    const float* vdwB_W2  = (const float*)d_in[25];
    const float* vdwB_b2  = (const float*)d_in[26];
    const float* hbond    = (const float*)d_in[27];
    const float* hydro    = (const float*)d_in[28];
    const float* vdwc     = (const float*)d_in[29];
    const float* rotc     = (const float*)d_in[30];
    float* out = (float*)d_out;

    float *g1p, *g2p, *hp_, *hAp, *ep, *attp, *hpp, *p1a, *p1b, *p2a, *p2b, *partp;
    cudaGetSymbolAddress((void**)&g1p,  g_g1);
    cudaGetSymbolAddress((void**)&g2p,  g_g2);
    cudaGetSymbolAddress((void**)&hp_,  g_h);
    cudaGetSymbolAddress((void**)&hAp,  g_hA);
    cudaGetSymbolAddress((void**)&ep,   g_e);
    cudaGetSymbolAddress((void**)&attp, g_att);
    cudaGetSymbolAddress((void**)&hpp,  g_hp);
    cudaGetSymbolAddress((void**)&p1a,  g_P1A);
    cudaGetSymbolAddress((void**)&p1b,  g_P1B);
    cudaGetSymbolAddress((void**)&p2a,  g_P2A);
    cudaGetSymbolAddress((void**)&p2b,  g_P2B);
    cudaGetSymbolAddress((void**)&partp, g_part);

    // 1. node embedding
    k_embed<<<BB*NN1, 128>>>(h1, node_W, g1p);
    k_embed<<<BB*NN2, 128>>>(h2, node_W, g2p);

    // 2. GAT layers (shared weights between the two graphs)
    for (int l = 0; l < 3; l++) {
        run_gat_layer(g1p, adj1, NN1, l, gat_W, gat_b, gat_A, gate_W, gate_b,
                      hp_, hAp, ep, attp, hpp);
        run_gat_layer(g2p, adj2, NN2, l, gat_W, gat_b, gat_A, gate_W, gate_b,
                      hp_, hAp, ep, attp, hpp);
    }

    // 3. pair-MLP projections (fold hidden bias b1 into the g1 side once)
    k_linear<<<BB*NN1, 128>>>(g1p, vdwA_W1,            vdwA_b1, p1a);
    k_linear<<<BB*NN1, 128>>>(g1p, vdwB_W1,            vdwB_b1, p1b);
    k_linear<<<BB*NN2, 128>>>(g2p, vdwA_W1 + DD*DD,    nullptr, p2a);
    k_linear<<<BB*NN2, 128>>>(g2p, vdwB_W1 + DD*DD,    nullptr, p2b);

    // 4. pairwise physics + per-(b,i) partial reduction
    k_pair<<<BB*NN1, 128>>>(p1a, p1b, p2a, p2b, vdwA_W2, vdwB_W2, vdwA_b2, vdwB_b2,
                            pos1, pos2, vdw_r1, vdw_r2, nm1, nm2, A_int, partp);

    // 5. final reduce + scaling
    k_final<<<BB, 128>>>(partp, rotor, duff, hbond, hydro, vdwc, rotc, out);
}

// round 2
// speedup vs baseline: 1.0666x; 1.0666x over previous
#include <cuda_runtime.h>
#include <math.h>

#define BB  8
#define NN1 128
#define NN2 512
#define DD  128
#define NTOT (NN1 + NN2)          // 640 rows per batch combined
#define MROWS (BB * NTOT)         // 5120 combined rows

// ---------------- static device scratch (no runtime allocation) ----------------
__device__ float g_g  [MROWS * DD];   // g1 rows [0,1024), g2 rows [1024,5120)
__device__ float g_h  [MROWS * DD];
__device__ float g_hA [MROWS * DD];
__device__ float g_hp [MROWS * DD];
__device__ float g_e  [BB * NN2 * NN2];
__device__ float g_att[BB * NN2 * NN2];
__device__ float g_P1A[BB * NN1 * DD];
__device__ float g_P1B[BB * NN1 * DD];
__device__ float g_P2A[BB * NN2 * DD];
__device__ float g_P2B[BB * NN2 * DD];
__device__ float g_part[BB * NN1 * 4];

// ---------------- kernels ----------------

// Embedding for both graphs in one launch. block = 128 threads = output dim.
__global__ void k_embed_both(const float* __restrict__ X1, const float* __restrict__ X2,
                             const float* __restrict__ W, float* __restrict__ Y) {
    int bn = blockIdx.x;               // 0..5119 combined row
    const float* src;
    if (bn < BB * NN1) src = X1 + (size_t)bn * 54;
    else               src = X2 + (size_t)(bn - BB * NN1) * 54;
    __shared__ float xs[54];
    if (threadIdx.x < 54) xs[threadIdx.x] = src[threadIdx.x];
    __syncthreads();
    int d = threadIdx.x;
    float acc = 0.f;
    #pragma unroll
    for (int l = 0; l < 54; l++) acc += xs[l] * W[l * DD + d];
    Y[(size_t)bn * DD + d] = acc;
}

// Batched C = act(A @ B + bias).  A:[M,K] rows, B:[K,N] row-major. 64x64 tile.
template<int RELU>
__global__ void k_gemm_nn(const float* __restrict__ A, const float* __restrict__ B,
                          const float* __restrict__ bias, float* __restrict__ C,
                          int M, int N, int K, long sA, long sB, long sC) {
    __shared__ float As[16][68];   // [k][m]
    __shared__ float Bs[16][68];   // [k][n]
    int b = blockIdx.z;
    A += (long)b * sA; B += (long)b * sB; C += (long)b * sC;
    int m0 = blockIdx.y * 64, n0 = blockIdx.x * 64;
    int tid = threadIdx.x;
    int tx = tid & 15, ty = tid >> 4;
    int lm = tid >> 2, lkq = (tid & 3) * 4;    // A loader: row lm, 4 k's
    int lk = tid >> 4, ln = (tid & 15) * 4;    // B loader: row lk, 4 n's
    float acc[4][4] = {};
    for (int k0 = 0; k0 < K; k0 += 16) {
        float4 a4 = *(const float4*)&A[(long)(m0 + lm) * K + k0 + lkq];
        As[lkq + 0][lm] = a4.x; As[lkq + 1][lm] = a4.y;
        As[lkq + 2][lm] = a4.z; As[lkq + 3][lm] = a4.w;
        *(float4*)&Bs[lk][ln] = *(const float4*)&B[(long)(k0 + lk) * N + n0 + ln];
        __syncthreads();
        #pragma unroll
        for (int k = 0; k < 16; k++) {
            float4 av = *(float4*)&As[k][ty * 4];
            float4 bv = *(float4*)&Bs[k][tx * 4];
            float am[4] = {av.x, av.y, av.z, av.w};
            float bn_[4] = {bv.x, bv.y, bv.z, bv.w};
            #pragma unroll
            for (int i = 0; i < 4; i++)
                #pragma unroll
                for (int j = 0; j < 4; j++)
                    acc[i][j] += am[i] * bn_[j];
        }
        __syncthreads();
    }
    #pragma unroll
    for (int i = 0; i < 4; i++) {
        int m = m0 + ty * 4 + i;
        int n = n0 + tx * 4;
        float4 v;
        float b0 = bias ? bias[n + 0] : 0.f;
        float b1 = bias ? bias[n + 1] : 0.f;
        float b2 = bias ? bias[n + 2] : 0.f;
        float b3 = bias ? bias[n + 3] : 0.f;
        v.x = acc[i][0] + b0; v.y = acc[i][1] + b1;
        v.z = acc[i][2] + b2; v.w = acc[i][3] + b3;
        if (RELU) {
            v.x = fmaxf(v.x, 0.f); v.y = fmaxf(v.y, 0.f);
            v.z = fmaxf(v.z, 0.f); v.w = fmaxf(v.w, 0.f);
        }
        *(float4*)&C[(long)m * N + n] = v;
    }
}

// Batched C = A @ B^T.  A:[M,K], B:[N,K] (both row-major). 64x64 tile.
__global__ void k_gemm_nt(const float* __restrict__ A, const float* __restrict__ B,
                          float* __restrict__ C, int M, int N, int K,
                          long sA, long sB, long sC) {
    __shared__ float As[16][68];
    __shared__ float Bs[16][68];
    int b = blockIdx.z;
    A += (long)b * sA; B += (long)b * sB; C += (long)b * sC;
    int m0 = blockIdx.y * 64, n0 = blockIdx.x * 64;
    int tid = threadIdx.x;
    int tx = tid & 15, ty = tid >> 4;
    int lm = tid >> 2, lkq = (tid & 3) * 4;
    float acc[4][4] = {};
    for (int k0 = 0; k0 < K; k0 += 16) {
        float4 a4 = *(const float4*)&A[(long)(m0 + lm) * K + k0 + lkq];
        As[lkq + 0][lm] = a4.x; As[lkq + 1][lm] = a4.y;
        As[lkq + 2][lm] = a4.z; As[lkq + 3][lm] = a4.w;
        float4 b4 = *(const float4*)&B[(long)(n0 + lm) * K + k0 + lkq];
        Bs[lkq + 0][lm] = b4.x; Bs[lkq + 1][lm] = b4.y;
        Bs[lkq + 2][lm] = b4.z; Bs[lkq + 3][lm] = b4.w;
        __syncthreads();
        #pragma unroll
        for (int k = 0; k < 16; k++) {
            float4 av = *(float4*)&As[k][ty * 4];
            float4 bv = *(float4*)&Bs[k][tx * 4];
            float am[4] = {av.x, av.y, av.z, av.w};
            float bn_[4] = {bv.x, bv.y, bv.z, bv.w};
            #pragma unroll
            for (int i = 0; i < 4; i++)
                #pragma unroll
                for (int j = 0; j < 4; j++)
                    acc[i][j] += am[i] * bn_[j];
        }
        __syncthreads();
    }
    #pragma unroll
    for (int i = 0; i < 4; i++) {
        int m = m0 + ty * 4 + i;
        int n = n0 + tx * 4;
        float4 v = {acc[i][0], acc[i][1], acc[i][2], acc[i][3]};
        *(float4*)&C[(long)m * N + n] = v;
    }
}

// Fused: L[i,k] = adj>0 ? E[i,k]+E[k,i] : -9e15 ; att = softmax over i (axis=1).
// (final *adj is a provable no-op: masked entries underflow to exact 0, adj is 0/1)
// block = (32 cols, 8 rows); dynamic smem Ls[N][33].
template<int N>
__global__ void k_softmax_fused(const float* __restrict__ E, const float* __restrict__ adj,
                                float* __restrict__ att) {
    extern __shared__ float Ls[];        // N*33
    __shared__ float Ts[32][33];
    __shared__ float red[8][33];
    int b = blockIdx.y;
    int k0 = blockIdx.x * 32;
    const float* Eb = E + (size_t)b * N * N;
    const float* Ab = adj + (size_t)b * N * N;
    float* Ob = att + (size_t)b * N * N;
    int tx = threadIdx.x, ty = threadIdx.y;
    for (int i0 = 0; i0 < N; i0 += 32) {
        #pragma unroll
        for (int r = ty; r < 32; r += 8)
            Ts[r][tx] = Eb[(size_t)(k0 + r) * N + i0 + tx];
        __syncthreads();
        #pragma unroll
        for (int r = ty; r < 32; r += 8) {
            float d = Eb[(size_t)(i0 + r) * N + k0 + tx];
            float a = Ab[(size_t)(i0 + r) * N + k0 + tx];
            float v = d + Ts[tx][r];
            Ls[(i0 + r) * 33 + tx] = (a > 0.f) ? v : -9e15f;
        }
        __syncthreads();
    }
    // column max over i
    float m = -3.4e38f;
    for (int i = ty; i < N; i += 8) m = fmaxf(m, Ls[i * 33 + tx]);
    red[ty][tx] = m;
    __syncthreads();
    if (ty == 0) {
        float mm = red[0][tx];
        #pragma unroll
        for (int y = 1; y < 8; y++) mm = fmaxf(mm, red[y][tx]);
        red[0][tx] = mm;
    }
    __syncthreads();
    m = red[0][tx];
    __syncthreads();
    float s = 0.f;
    for (int i = ty; i < N; i += 8) {
        float e = __expf(Ls[i * 33 + tx] - m);
        Ls[i * 33 + tx] = e;
        s += e;
    }
    red[ty][tx] = s;
    __syncthreads();
    if (ty == 0) {
        float ss = 0.f;
        #pragma unroll
        for (int y = 0; y < 8; y++) ss += red[y][tx];
        red[0][tx] = ss;
    }
    __syncthreads();
    float inv = 1.f / red[0][tx];
    for (int i = ty; i < N; i += 8)
        Ob[(size_t)i * N + k0 + tx] = Ls[i * 33 + tx] * inv;
}

// gated residual over all 5120 rows: c = sigmoid(x.gW[:D] + hp.gW[D:] + gb)
__global__ void k_gate(float* __restrict__ g, const float* __restrict__ hp,
                       const float* __restrict__ gW, const float* __restrict__ gb) {
    int bn = blockIdx.x, t = threadIdx.x;
    size_t base = (size_t)bn * DD;
    float x = g[base + t], h = hp[base + t];
    float v = x * gW[t] + h * gW[DD + t];
    #pragma unroll
    for (int o = 16; o > 0; o >>= 1) v += __shfl_down_sync(0xffffffffu, v, o);
    __shared__ float red[4];
    __shared__ float csh;
    if ((t & 31) == 0) red[t >> 5] = v;
    __syncthreads();
    if (t == 0) {
        float s = red[0] + red[1] + red[2] + red[3] + gb[0];
        csh = 1.f / (1.f + __expf(-s));
    }
    __syncthreads();
    float c = csh;
    g[base + t] = c * x + (1.f - c) * h;
}

// per-(b,i): all j, both pair MLPs + physics, partial sums -> part
__global__ void k_pair(const float* __restrict__ P1A, const float* __restrict__ P1B,
                       const float* __restrict__ P2A, const float* __restrict__ P2B,
                       const float* __restrict__ w2A, const float* __restrict__ w2B,
                       const float* __restrict__ b2A, const float* __restrict__ b2B,
                       const float* __restrict__ pos1, const float* __restrict__ pos2,
                       const float* __restrict__ r1, const float* __restrict__ r2,
                       const float* __restrict__ nm1, const float* __restrict__ nm2,
                       const float* __restrict__ A_int, float* __restrict__ part) {
    int b = blockIdx.x >> 7;
    int i = blockIdx.x & 127;
    int t = threadIdx.x, lane = t & 31, w = t >> 5;
    __shared__ float p1a[DD], p1b[DD], w2a[DD], w2b[DD];
    size_t rbase = ((size_t)b * NN1 + i) * DD;
    p1a[t] = P1A[rbase + t];
    p1b[t] = P1B[rbase + t];
    w2a[t] = w2A[t];
    w2b[t] = w2B[t];
    __syncthreads();
    float px = pos1[(b * NN1 + i) * 3 + 0];
    float py = pos1[(b * NN1 + i) * 3 + 1];
    float pz = pos1[(b * NN1 + i) * 3 + 2];
    float rr1 = r1[b * NN1 + i];
    float m1  = nm1[b * NN1 + i];
    float b2a = b2A[0], b2b = b2B[0];
    size_t a_base = (size_t)b * 8 * NN1 * NN2 + (size_t)i * NN2;
    const size_t chw = (size_t)NN1 * NN2;
    float s0 = 0.f, s1 = 0.f, s2 = 0.f, s3 = 0.f;
    for (int j = w; j < NN2; j += 4) {
        const float* p2a = P2A + ((size_t)b * NN2 + j) * DD;
        const float* p2b = P2B + ((size_t)b * NN2 + j) * DD;
        float za = 0.f, zb = 0.f;
        #pragma unroll
        for (int hh = 0; hh < 4; hh++) {
            int h = lane + hh * 32;
            za += fmaxf(p1a[h] + p2a[h], 0.f) * w2a[h];
            zb += fmaxf(p1b[h] + p2b[h], 0.f) * w2b[h];
        }
        #pragma unroll
        for (int o = 16; o > 0; o >>= 1) {
            za += __shfl_down_sync(0xffffffffu, za, o);
            zb += __shfl_down_sync(0xffffffffu, zb, o);
        }
        if (lane == 0) {
            za += b2a; zb += b2b;
            float Aw = 1.f / (1.f + __expf(-za));
            float Bw = tanhf(zb) * 0.2f;
            float dx = px - pos2[(b * NN2 + j) * 3 + 0];
            float dy = py - pos2[(b * NN2 + j) * 3 + 1];
            float dz = pz - pos2[(b * NN2 + j) * 3 + 2];
            float dm = sqrtf(dx * dx + dy * dy + dz * dz + 1e-10f);
            if (dm < 0.5f) dm = 1e10f;
            float dm0 = rr1 + r2[b * NN2 + j] + Bw;
            float dm0s = (dm0 < 1e-4f) ? 1.f : dm0;
            float rq = dm0s / dm;
            float rq2 = rq * rq;
            float r6 = rq2 * rq2 * rq2;
            float evdw = fminf(r6 * r6 - 2.f * r6, 100.f);
            float Aamp = Aw * (0.0356f - 0.0178f) + 0.0178f;
            s0 += Aamp * evdw * m1 * nm2[b * NN2 + j];
            float dmd = dm - dm0;
            float a1 = A_int[a_base + 1 * chw + j];
            float a7 = A_int[a_base + 7 * chw + j];
            float a6 = A_int[a_base + 6 * chw + j];
            s1 += fminf(fmaxf(dmd * a1 * (-1.f / 0.7f), 0.f), 1.f);
            s2 += fminf(fmaxf(dmd * a7 * (-1.f / 0.7f), 0.f), 1.f);
            s3 += fminf(fmaxf((1.5f - dmd) * a6, 0.f), 1.f);
        }
    }
    __shared__ float acc[4][4];
    if (lane == 0) { acc[w][0] = s0; acc[w][1] = s1; acc[w][2] = s2; acc[w][3] = s3; }
    __syncthreads();
    if (t < 4) {
        part[((size_t)b * NN1 + i) * 4 + t] = acc[0][t] + acc[1][t] + acc[2][t] + acc[3][t];
    }
}

__global__ void k_final(const float* __restrict__ part, const float* __restrict__ rotor,
                        const float* __restrict__ duff, const float* __restrict__ hbc,
                        const float* __restrict__ hyc, const float* __restrict__ vdc,
                        const float* __restrict__ rtc, float* __restrict__ out) {
    int b = blockIdx.x, t = threadIdx.x;
    size_t base = ((size_t)b * NN1 + t) * 4;
    float v0 = part[base + 0], v1 = part[base + 1], v2 = part[base + 2], v3 = part[base + 3];
    #pragma unroll
    for (int o = 16; o > 0; o >>= 1) {
        v0 += __shfl_down_sync(0xffffffffu, v0, o);
        v1 += __shfl_down_sync(0xffffffffu, v1, o);
        v2 += __shfl_down_sync(0xffffffffu, v2, o);
        v3 += __shfl_down_sync(0xffffffffu, v3, o);
    }
    __shared__ float red[4][4];
    if ((t & 31) == 0) {
        int w = t >> 5;
        red[w][0] = v0; red[w][1] = v1; red[w][2] = v2; red[w][3] = v3;
    }
    __syncthreads();
    if (t == 0) {
        float s0 = red[0][0] + red[1][0] + red[2][0] + red[3][0];
        float s1 = red[0][1] + red[1][1] + red[2][1] + red[3][1];
        float s2 = red[0][2] + red[1][2] + red[2][2] + red[3][2];
        float s3 = red[0][3] + red[1][3] + red[2][3] + red[3][3];
        float hb = -hbc[0] * hbc[0];
        float hy = -hyc[0] * hyc[0];
        float inv = 1.f / (1.f + rtc[0] * rtc[0] * rotor[b]);
        out[b * 5 + 0] = s0 * inv;
        out[b * 5 + 1] = s1 * hb * inv;
        out[b * 5 + 2] = s2 * hb * inv;
        out[b * 5 + 3] = s3 * hy * inv;
        out[b * 5 + 4] = duff[b] * vdc[0] * vdc[0] * inv;
    }
}

// ---------------- host side ----------------

extern "C" void kernel_launch(void* const* d_in, const int* in_sizes, int n_in,
                              void* d_out, int out_size) {
    (void)in_sizes; (void)n_in; (void)out_size;
    const float* h1      = (const float*)d_in[0];
    const float* adj1    = (const float*)d_in[1];
    const float* h2      = (const float*)d_in[2];
    const float* adj2    = (const float*)d_in[3];
    const float* A_int   = (const float*)d_in[4];
    const float* pos1    = (const float*)d_in[5];
    const float* pos2    = (const float*)d_in[6];
    const float* rotor   = (const float*)d_in[7];
    const float* vdw_r1  = (const float*)d_in[8];
    const float* vdw_r2  = (const float*)d_in[9];
    const float* duff    = (const float*)d_in[10];
    const float* nm1     = (const float*)d_in[11];
    const float* nm2     = (const float*)d_in[12];
    const float* node_W  = (const float*)d_in[13];
    const float* gat_W   = (const float*)d_in[14];
    const float* gat_b   = (const float*)d_in[15];
    const float* gat_A   = (const float*)d_in[16];
    const float* gate_W  = (const float*)d_in[17];
    const float* gate_b  = (const float*)d_in[18];
    const float* vdwA_W1 = (const float*)d_in[19];
    const float* vdwA_b1 = (const float*)d_in[20];
    const float* vdwA_W2 = (const float*)d_in[21];
    const float* vdwA_b2 = (const float*)d_in[22];
    const float* vdwB_W1 = (const float*)d_in[23];
    const float* vdwB_b1 = (const float*)d_in[24];
    const float* vdwB_W2 = (const float*)d_in[25];
    const float* vdwB_b2 = (const float*)d_in[26];
    const float* hbond   = (const float*)d_in[27];
    const float* hydro   = (const float*)d_in[28];
    const float* vdwc    = (const float*)d_in[29];
    const float* rotc    = (const float*)d_in[30];
    float* out = (float*)d_out;

    float *gp, *hp_, *hAp, *hpp, *ep, *attp, *p1a, *p1b, *p2a, *p2b, *partp;
    cudaGetSymbolAddress((void**)&gp,   g_g);
    cudaGetSymbolAddress((void**)&hp_,  g_h);
    cudaGetSymbolAddress((void**)&hAp,  g_hA);
    cudaGetSymbolAddress((void**)&hpp,  g_hp);
    cudaGetSymbolAddress((void**)&ep,   g_e);
    cudaGetSymbolAddress((void**)&attp, g_att);
    cudaGetSymbolAddress((void**)&p1a,  g_P1A);
    cudaGetSymbolAddress((void**)&p1b,  g_P1B);
    cudaGetSymbolAddress((void**)&p2a,  g_P2A);
    cudaGetSymbolAddress((void**)&p2b,  g_P2B);
    cudaGetSymbolAddress((void**)&partp, g_part);

    // allow >48KB dynamic smem for the N=512 softmax
    cudaFuncSetAttribute(k_softmax_fused<NN2>,
                         cudaFuncAttributeMaxDynamicSharedMemorySize, NN2 * 33 * 4);
    cudaFuncSetAttribute(k_softmax_fused<NN1>,
                         cudaFuncAttributeMaxDynamicSharedMemorySize, NN1 * 33 * 4);

    const long R1 = (long)BB * NN1;       // 1024 graph-1 rows
    float* g1 = gp;
    float* g2 = gp + R1 * DD;
    float* h1b = hp_;
    float* h2b = hp_ + R1 * DD;
    float* hA1 = hAp;
    float* hA2 = hAp + R1 * DD;
    float* hp1 = hpp;
    float* hp2 = hpp + R1 * DD;

    // 1. embedding (both graphs, one launch)
    k_embed_both<<<MROWS, 128>>>(h1, h2, node_W, gp);

    // 2. GAT layers
    for (int l = 0; l < 3; l++) {
        const float* W  = gat_W  + (size_t)l * DD * DD;
        const float* bW = gat_b  + (size_t)l * DD;
        const float* Am = gat_A  + (size_t)l * DD * DD;
        const float* gW = gate_W + (size_t)l * 2 * DD;
        const float* gb = gate_b + l;

        // h = g @ W + b   (combined 5120 rows)
        k_gemm_nn<0><<<dim3(DD / 64, MROWS / 64, 1), 256>>>(gp, W, bW, hp_,
                                                            MROWS, DD, DD, 0, 0, 0);
        // hA = h @ A
        k_gemm_nn<0><<<dim3(DD / 64, MROWS / 64, 1), 256>>>(hp_, Am, nullptr, hAp,
                                                            MROWS, DD, DD, 0, 0, 0);
        // e = hA @ h^T per batch (graph 2 first: bigger grid keeps SMs busy)
        k_gemm_nt<<<dim3(NN2 / 64, NN2 / 64, BB), 256>>>(hA2, h2b, ep, NN2, NN2, DD,
                                                         (long)NN2 * DD, (long)NN2 * DD,
                                                         (long)NN2 * NN2);
        k_softmax_fused<NN2><<<dim3(NN2 / 32, BB), dim3(32, 8), NN2 * 33 * 4>>>(ep, adj2, attp);
        // hp2 = relu(att2 @ h2)
        k_gemm_nn<1><<<dim3(DD / 64, NN2 / 64, BB), 256>>>(attp, h2b, nullptr, hp2,
                                                           NN2, DD, NN2,
                                                           (long)NN2 * NN2, (long)NN2 * DD,
                                                           (long)NN2 * DD);
        // graph 1
        k_gemm_nt<<<dim3(NN1 / 64, NN1 / 64, BB), 256>>>(hA1, h1b, ep, NN1, NN1, DD,
                                                         (long)NN1 * DD, (long)NN1 * DD,
                                                         (long)NN1 * NN1);
        k_softmax_fused<NN1><<<dim3(NN1 / 32, BB), dim3(32, 8), NN1 * 33 * 4>>>(ep, adj1, attp);
        k_gemm_nn<1><<<dim3(DD / 64, NN1 / 64, BB), 256>>>(attp, h1b, nullptr, hp1,
                                                           NN1, DD, NN1,
                                                           (long)NN1 * NN1, (long)NN1 * DD,
                                                           (long)NN1 * DD);
        // gated residual (combined)
        k_gate<<<MROWS, 128>>>(gp, hpp, gW, gb);
    }

    // 3. pair-MLP projections (b1 folded into the g1 side)
    k_gemm_nn<0><<<dim3(DD / 64, (int)(R1 / 64), 1), 256>>>(g1, vdwA_W1, vdwA_b1, p1a,
                                                            (int)R1, DD, DD, 0, 0, 0);
    k_gemm_nn<0><<<dim3(DD / 64, (int)(R1 / 64), 1), 256>>>(g1, vdwB_W1, vdwB_b1, p1b,
                                                            (int)R1, DD, DD, 0, 0, 0);
    k_gemm_nn<0><<<dim3(DD / 64, (BB * NN2) / 64, 1), 256>>>(g2, vdwA_W1 + DD * DD, nullptr, p2a,
                                                             BB * NN2, DD, DD, 0, 0, 0);
    k_gemm_nn<0><<<dim3(DD / 64, (BB * NN2) / 64, 1), 256>>>(g2, vdwB_W1 + DD * DD, nullptr, p2b,
                                                             BB * NN2, DD, DD, 0, 0, 0);

    // 4. pairwise physics + per-(b,i) partial reduction
    k_pair<<<BB * NN1, 128>>>(p1a, p1b, p2a, p2b, vdwA_W2, vdwB_W2, vdwA_b2, vdwB_b2,
                              pos1, pos2, vdw_r1, vdw_r2, nm1, nm2, A_int, partp);

    // 5. final reduce + scaling
    k_final<<<BB, 128>>>(partp, rotor, duff, hbond, hydro, vdwc, rotc, out);
}

// round 4
// speedup vs baseline: 1.2721x; 1.1927x over previous
#include <cuda_runtime.h>
#include <math.h>

#define BB  8
#define NN1 128
#define NN2 512
#define DD  128
#define MROWS (BB * (NN1 + NN2))   // 5120 combined rows
#define R1   (BB * NN1)            // 1024 graph-1 rows

// ---------------- static device scratch ----------------
__device__ float g_g  [MROWS * DD];
__device__ float g_h  [MROWS * DD];
__device__ float g_hA [MROWS * DD];
__device__ float g_e2 [BB * NN2 * NN2];
__device__ float g_a2 [BB * NN2 * NN2];
__device__ float g_e1 [BB * NN1 * NN1];
__device__ float g_a1 [BB * NN1 * NN1];
__device__ float g_WA [3 * DD * DD];
__device__ float g_bA [3 * DD];
__device__ float g_P1A[BB * NN1 * DD];
__device__ float g_P1B[BB * NN1 * DD];
__device__ float g_P2A[BB * NN2 * DD];
__device__ float g_P2B[BB * NN2 * DD];
__device__ float g_ZA [BB * NN1 * NN2];
__device__ float g_ZB [BB * NN1 * NN2];
__device__ float g_part[BB * NN1 * 4];

// ---------------- shared 64x64 GEMM body (A[M,K] @ B[K,N] + bias) ----------------
template<int RELU>
__device__ __forceinline__ void gemm64_body(const float* __restrict__ A,
                                            const float* __restrict__ B,
                                            const float* __restrict__ bias,
                                            float* __restrict__ C,
                                            int N, int K, int m0, int n0) {
    __shared__ float As[16][68];
    __shared__ float Bs[16][68];
    int tid = threadIdx.x;
    int tx = tid & 15, ty = tid >> 4;
    int lm = tid >> 2, lkq = (tid & 3) * 4;
    int lk = tid >> 4, ln = (tid & 15) * 4;
    float acc[4][4] = {};
    for (int k0 = 0; k0 < K; k0 += 16) {
        float4 a4 = *(const float4*)&A[(long)(m0 + lm) * K + k0 + lkq];
        As[lkq + 0][lm] = a4.x; As[lkq + 1][lm] = a4.y;
        As[lkq + 2][lm] = a4.z; As[lkq + 3][lm] = a4.w;
        *(float4*)&Bs[lk][ln] = *(const float4*)&B[(long)(k0 + lk) * N + n0 + ln];
        __syncthreads();
        #pragma unroll
        for (int k = 0; k < 16; k++) {
            float4 av = *(float4*)&As[k][ty * 4];
            float4 bv = *(float4*)&Bs[k][tx * 4];
            float am[4] = {av.x, av.y, av.z, av.w};
            float bn_[4] = {bv.x, bv.y, bv.z, bv.w};
            #pragma unroll
            for (int i = 0; i < 4; i++)
                #pragma unroll
                for (int j = 0; j < 4; j++)
                    acc[i][j] += am[i] * bn_[j];
        }
        __syncthreads();
    }
    #pragma unroll
    for (int i = 0; i < 4; i++) {
        int m = m0 + ty * 4 + i;
        int n = n0 + tx * 4;
        float4 v;
        v.x = acc[i][0] + (bias ? bias[n + 0] : 0.f);
        v.y = acc[i][1] + (bias ? bias[n + 1] : 0.f);
        v.z = acc[i][2] + (bias ? bias[n + 2] : 0.f);
        v.w = acc[i][3] + (bias ? bias[n + 3] : 0.f);
        if (RELU) {
            v.x = fmaxf(v.x, 0.f); v.y = fmaxf(v.y, 0.f);
            v.z = fmaxf(v.z, 0.f); v.w = fmaxf(v.w, 0.f);
        }
        *(float4*)&C[(long)m * N + n] = v;
    }
}

// WA[l] = gat_W[l] @ gat_A[l]
__global__ void k_wa(const float* __restrict__ W, const float* __restrict__ A,
                     float* __restrict__ WA) {
    int l = blockIdx.z;
    gemm64_body<0>(W + (long)l * DD * DD, A + (long)l * DD * DD, nullptr,
                   WA + (long)l * DD * DD, DD, DD, blockIdx.y * 64, blockIdx.x * 64);
}

// bA[l] = gat_b[l] @ gat_A[l]
__global__ void k_bvec(const float* __restrict__ b, const float* __restrict__ A,
                       float* __restrict__ bA) {
    int l = blockIdx.x, n = threadIdx.x;
    float acc = 0.f;
    #pragma unroll 8
    for (int k = 0; k < DD; k++)
        acc += b[l * DD + k] * A[((long)l * DD + k) * DD + n];
    bA[l * DD + n] = acc;
}

// embedding for both graphs
__global__ void k_embed_both(const float* __restrict__ X1, const float* __restrict__ X2,
                             const float* __restrict__ W, float* __restrict__ Y) {
    int bn = blockIdx.x;
    const float* src = (bn < R1) ? X1 + (size_t)bn * 54
                                 : X2 + (size_t)(bn - R1) * 54;
    __shared__ float xs[54];
    if (threadIdx.x < 54) xs[threadIdx.x] = src[threadIdx.x];
    __syncthreads();
    int d = threadIdx.x;
    float acc = 0.f;
    #pragma unroll
    for (int l = 0; l < 54; l++) acc += xs[l] * W[l * DD + d];
    Y[(size_t)bn * DD + d] = acc;
}

// h = g@W + b ; hA = g@WA + bA  (one launch, 5120 rows)
__global__ void k_dual(const float* __restrict__ g, const float* __restrict__ W,
                       const float* __restrict__ b, const float* __restrict__ WA,
                       const float* __restrict__ bA, float* __restrict__ h,
                       float* __restrict__ hA) {
    int xi = blockIdx.x;
    const float* B; const float* bias; float* C; int n0;
    if (xi < 2) { B = W;  bias = b;  C = h;  n0 = xi * 64; }
    else        { B = WA; bias = bA; C = hA; n0 = (xi - 2) * 64; }
    gemm64_body<0>(g, B, bias, C, DD, DD, blockIdx.y * 64, n0);
}

// e = hA @ h^T, both graphs (z<8: graph2 N=512; z>=8: graph1 N=128)
__global__ void k_nt_both(const float* __restrict__ h, const float* __restrict__ hA,
                          float* __restrict__ e2, float* __restrict__ e1) {
    int z = blockIdx.z;
    int N; const float* Ab; const float* Bb; float* Cb;
    if (z < 8) {
        N = NN2;
        Ab = hA + ((long)R1 + (long)z * NN2) * DD;
        Bb = h  + ((long)R1 + (long)z * NN2) * DD;
        Cb = e2 + (long)z * NN2 * NN2;
    } else {
        if (blockIdx.x >= 2 || blockIdx.y >= 2) return;
        N = NN1;
        Ab = hA + (long)(z - 8) * NN1 * DD;
        Bb = h  + (long)(z - 8) * NN1 * DD;
        Cb = e1 + (long)(z - 8) * NN1 * NN1;
    }
    __shared__ float As[16][68];
    __shared__ float Bs[16][68];
    int m0 = blockIdx.y * 64, n0 = blockIdx.x * 64;
    int tid = threadIdx.x;
    int tx = tid & 15, ty = tid >> 4;
    int lm = tid >> 2, lkq = (tid & 3) * 4;
    float acc[4][4] = {};
    for (int k0 = 0; k0 < DD; k0 += 16) {
        float4 a4 = *(const float4*)&Ab[(long)(m0 + lm) * DD + k0 + lkq];
        As[lkq + 0][lm] = a4.x; As[lkq + 1][lm] = a4.y;
        As[lkq + 2][lm] = a4.z; As[lkq + 3][lm] = a4.w;
        float4 b4 = *(const float4*)&Bb[(long)(n0 + lm) * DD + k0 + lkq];
        Bs[lkq + 0][lm] = b4.x; Bs[lkq + 1][lm] = b4.y;
        Bs[lkq + 2][lm] = b4.z; Bs[lkq + 3][lm] = b4.w;
        __syncthreads();
        #pragma unroll
        for (int k = 0; k < 16; k++) {
            float4 av = *(float4*)&As[k][ty * 4];
            float4 bv = *(float4*)&Bs[k][tx * 4];
            float am[4] = {av.x, av.y, av.z, av.w};
            float bn_[4] = {bv.x, bv.y, bv.z, bv.w};
            #pragma unroll
            for (int i = 0; i < 4; i++)
                #pragma unroll
                for (int j = 0; j < 4; j++)
                    acc[i][j] += am[i] * bn_[j];
        }
        __syncthreads();
    }
    #pragma unroll
    for (int i = 0; i < 4; i++) {
        int m = m0 + ty * 4 + i, n = n0 + tx * 4;
        float4 v = {acc[i][0], acc[i][1], acc[i][2], acc[i][3]};
        *(float4*)&Cb[(long)m * N + n] = v;
    }
}

// fused symmetrize + mask + column softmax (axis=1), both graphs
__global__ void k_softmax_both(const float* __restrict__ e2, const float* __restrict__ adj2,
                               float* __restrict__ a2, const float* __restrict__ e1,
                               const float* __restrict__ adj1, float* __restrict__ a1) {
    extern __shared__ float Ls[];   // N*33 floats
    __shared__ float Ts[32][33];
    __shared__ float red[8][33];
    int z = blockIdx.y;
    int N; const float* Eb; const float* Ab; float* Ob;
    if (z < 8) {
        N = NN2;
        Eb = e2 + (long)z * NN2 * NN2; Ab = adj2 + (long)z * NN2 * NN2;
        Ob = a2 + (long)z * NN2 * NN2;
    } else {
        if (blockIdx.x >= NN1 / 32) return;
        N = NN1;
        Eb = e1 + (long)(z - 8) * NN1 * NN1; Ab = adj1 + (long)(z - 8) * NN1 * NN1;
        Ob = a1 + (long)(z - 8) * NN1 * NN1;
    }
    int k0 = blockIdx.x * 32;
    int tx = threadIdx.x, ty = threadIdx.y;
    for (int i0 = 0; i0 < N; i0 += 32) {
        for (int r = ty; r < 32; r += 8)
            Ts[r][tx] = Eb[(size_t)(k0 + r) * N + i0 + tx];
        __syncthreads();
        for (int r = ty; r < 32; r += 8) {
            float d = Eb[(size_t)(i0 + r) * N + k0 + tx];
            float a = Ab[(size_t)(i0 + r) * N + k0 + tx];
            Ls[(i0 + r) * 33 + tx] = (a > 0.f) ? (d + Ts[tx][r]) : -9e15f;
        }
        __syncthreads();
    }
    float m = -3.4e38f;
    for (int i = ty; i < N; i += 8) m = fmaxf(m, Ls[i * 33 + tx]);
    red[ty][tx] = m;
    __syncthreads();
    if (ty == 0) {
        float mm = red[0][tx];
        #pragma unroll
        for (int y = 1; y < 8; y++) mm = fmaxf(mm, red[y][tx]);
        red[0][tx] = mm;
    }
    __syncthreads();
    m = red[0][tx];
    __syncthreads();
    float s = 0.f;
    for (int i = ty; i < N; i += 8) {
        float e = __expf(Ls[i * 33 + tx] - m);
        Ls[i * 33 + tx] = e;
        s += e;
    }
    red[ty][tx] = s;
    __syncthreads();
    if (ty == 0) {
        float ss = 0.f;
        #pragma unroll
        for (int y = 0; y < 8; y++) ss += red[y][tx];
        red[0][tx] = ss;
    }
    __syncthreads();
    float inv = 1.f / red[0][tx];
    for (int i = ty; i < N; i += 8)
        Ob[(size_t)i * N + k0 + tx] = Ls[i * 33 + tx] * inv;
}

// fused: hp = relu(att @ h); c = sigmoid(g.gW1 + hp.gW2 + gb); g = c*g + (1-c)*hp
// tile 32 rows x 128 cols. z<8: graph2 (M=K=512); z>=8: graph1 (M=K=128).
__global__ void k_relugate(const float* __restrict__ a2, const float* __restrict__ a1,
                           const float* __restrict__ h, float* __restrict__ g,
                           const float* __restrict__ gW, const float* __restrict__ gb) {
    int z = blockIdx.z;
    int M, K; const float* att; const float* Hb; float* G;
    if (z < 8) {
        M = NN2; K = NN2;
        att = a2 + (long)z * NN2 * NN2;
        Hb = h + ((long)R1 + (long)z * NN2) * DD;
        G  = g + ((long)R1 + (long)z * NN2) * DD;
    } else {
        M = NN1; K = NN1;
        att = a1 + (long)(z - 8) * NN1 * NN1;
        Hb = h + (long)(z - 8) * NN1 * DD;
        G  = g + (long)(z - 8) * NN1 * DD;
    }
    int m0 = blockIdx.y * 32;
    if (m0 >= M) return;
    __shared__ float As[16][36];
    __shared__ float Bs[16][132];
    __shared__ float gw1[DD], gw2[DD];
    __shared__ float redH[32][17], redX[32][17];
    __shared__ float csm[32];
    int tid = threadIdx.x;
    int tx = tid & 15, ty = tid >> 4;
    if (tid < DD) { gw1[tid] = gW[tid]; gw2[tid] = gW[DD + tid]; }
    float acc[2][8] = {};
    for (int k0 = 0; k0 < K; k0 += 16) {
        if (tid < 128) {
            int ar = tid >> 2, akq = (tid & 3) * 4;
            float4 a4 = *(const float4*)&att[(long)(m0 + ar) * K + k0 + akq];
            As[akq + 0][ar] = a4.x; As[akq + 1][ar] = a4.y;
            As[akq + 2][ar] = a4.z; As[akq + 3][ar] = a4.w;
        }
        int br = tid >> 4, bc = (tid & 15) * 8;
        *(float4*)&Bs[br][bc]     = *(const float4*)&Hb[(long)(k0 + br) * DD + bc];
        *(float4*)&Bs[br][bc + 4] = *(const float4*)&Hb[(long)(k0 + br) * DD + bc + 4];
        __syncthreads();
        #pragma unroll
        for (int k = 0; k < 16; k++) {
            float2 av = *(float2*)&As[k][ty * 2];
            float am[2] = {av.x, av.y};
            float4 b0 = *(float4*)&Bs[k][tx * 8];
            float4 b1 = *(float4*)&Bs[k][tx * 8 + 4];
            float bn_[8] = {b0.x, b0.y, b0.z, b0.w, b1.x, b1.y, b1.z, b1.w};
            #pragma unroll
            for (int i = 0; i < 2; i++)
                #pragma unroll
                for (int j = 0; j < 8; j++)
                    acc[i][j] += am[i] * bn_[j];
        }
        __syncthreads();
    }
    float xv[2][8];
    #pragma unroll
    for (int i = 0; i < 2; i++) {
        int m = m0 + ty * 2 + i;
        float4 x0 = *(const float4*)&G[(long)m * DD + tx * 8];
        float4 x1 = *(const float4*)&G[(long)m * DD + tx * 8 + 4];
        xv[i][0] = x0.x; xv[i][1] = x0.y; xv[i][2] = x0.z; xv[i][3] = x0.w;
        xv[i][4] = x1.x; xv[i][5] = x1.y; xv[i][6] = x1.z; xv[i][7] = x1.w;
    }
    #pragma unroll
    for (int i = 0; i < 2; i++) {
        float sh = 0.f, sx = 0.f;
        #pragma unroll
        for (int j = 0; j < 8; j++) {
            acc[i][j] = fmaxf(acc[i][j], 0.f);
            sh += acc[i][j] * gw2[tx * 8 + j];
            sx += xv[i][j] * gw1[tx * 8 + j];
        }
        redH[ty * 2 + i][tx] = sh;
        redX[ty * 2 + i][tx] = sx;
    }
    __syncthreads();
    if (tid < 32) {
        float s = 0.f;
        #pragma unroll
        for (int t = 0; t < 16; t++) s += redH[tid][t] + redX[tid][t];
        s += gb[0];
        csm[tid] = 1.f / (1.f + __expf(-s));
    }
    __syncthreads();
    #pragma unroll
    for (int i = 0; i < 2; i++) {
        int m = m0 + ty * 2 + i;
        float c = csm[ty * 2 + i];
        float4 v0, v1;
        v0.x = c * xv[i][0] + (1.f - c) * acc[i][0];
        v0.y = c * xv[i][1] + (1.f - c) * acc[i][1];
        v0.z = c * xv[i][2] + (1.f - c) * acc[i][2];
        v0.w = c * xv[i][3] + (1.f - c) * acc[i][3];
        v1.x = c * xv[i][4] + (1.f - c) * acc[i][4];
        v1.y = c * xv[i][5] + (1.f - c) * acc[i][5];
        v1.z = c * xv[i][6] + (1.f - c) * acc[i][6];
        v1.w = c * xv[i][7] + (1.f - c) * acc[i][7];
        *(float4*)&G[(long)m * DD + tx * 8]     = v0;
        *(float4*)&G[(long)m * DD + tx * 8 + 4] = v1;
    }
}

// all 4 pair projections in one launch (z: 0=p1a 1=p1b 2=p2a 3=p2b)
__global__ void k_proj(const float* __restrict__ g,
                       const float* __restrict__ WA1, const float* __restrict__ bA1,
                       const float* __restrict__ WB1, const float* __restrict__ bB1,
                       float* __restrict__ p1a, float* __restrict__ p1b,
                       float* __restrict__ p2a, float* __restrict__ p2b) {
    int z = blockIdx.z;
    const float* A; const float* B; const float* bias; float* C; int mt;
    switch (z) {
        case 0: A = g;            B = WA1;           bias = bA1;   C = p1a; mt = R1 / 64; break;
        case 1: A = g;            B = WB1;           bias = bB1;   C = p1b; mt = R1 / 64; break;
        case 2: A = g + (long)R1 * DD; B = WA1 + DD * DD; bias = nullptr; C = p2a; mt = (BB * NN2) / 64; break;
        default:A = g + (long)R1 * DD; B = WB1 + DD * DD; bias = nullptr; C = p2b; mt = (BB * NN2) / 64; break;
    }
    if ((int)blockIdx.y >= mt) return;
    gemm64_body<0>(A, B, bias, C, DD, DD, blockIdx.y * 64, blockIdx.x * 64);
}

// Z[b,i,j] = act( b2 + sum_h relu(P1[i,h]+P2[j,h]) * w2[h] ), 32x32 tiles
__global__ void k_zmat(const float* __restrict__ p1a, const float* __restrict__ p1b,
                       const float* __restrict__ p2a, const float* __restrict__ p2b,
                       const float* __restrict__ w2A, const float* __restrict__ w2B,
                       const float* __restrict__ b2A, const float* __restrict__ b2B,
                       float* __restrict__ ZA, float* __restrict__ ZB) {
    __shared__ float P1s[DD][33];
    __shared__ float P2s[DD][33];
    __shared__ float w2s[DD];
    int z = blockIdx.z;
    int b = z >> 1, mlp = z & 1;
    const float* P1 = (mlp ? p1b : p1a) + (long)b * NN1 * DD;
    const float* P2 = (mlp ? p2b : p2a) + (long)b * NN2 * DD;
    const float* w2 = mlp ? w2B : w2A;
    float b2 = mlp ? b2B[0] : b2A[0];
    float* Z = (mlp ? ZB : ZA) + (long)b * NN1 * NN2;
    int i0 = blockIdx.y * 32, j0 = blockIdx.x * 32;
    int tid = threadIdx.x;
    if (tid < DD) w2s[tid] = w2[tid];
    {
        int row = tid >> 3, cb = (tid & 7) * 16;
        #pragma unroll
        for (int q = 0; q < 4; q++) {
            float4 v1 = *(const float4*)&P1[(long)(i0 + row) * DD + cb + q * 4];
            float4 v2 = *(const float4*)&P2[(long)(j0 + row) * DD + cb + q * 4];
            P1s[cb + q * 4 + 0][row] = v1.x; P1s[cb + q * 4 + 1][row] = v1.y;
            P1s[cb + q * 4 + 2][row] = v1.z; P1s[cb + q * 4 + 3][row] = v1.w;
            P2s[cb + q * 4 + 0][row] = v2.x; P2s[cb + q * 4 + 1][row] = v2.y;
            P2s[cb + q * 4 + 2][row] = v2.z; P2s[cb + q * 4 + 3][row] = v2.w;
        }
    }
    __syncthreads();
    int tx = tid & 15, ty = tid >> 4;
    float a00 = 0.f, a01 = 0.f, a10 = 0.f, a11 = 0.f;
    #pragma unroll 4
    for (int k = 0; k < DD; k++) {
        float w = w2s[k];
        float p0 = P1s[k][ty], p1 = P1s[k][ty + 16];
        float q0 = P2s[k][tx], q1 = P2s[k][tx + 16];
        a00 += fmaxf(p0 + q0, 0.f) * w;
        a01 += fmaxf(p0 + q1, 0.f) * w;
        a10 += fmaxf(p1 + q0, 0.f) * w;
        a11 += fmaxf(p1 + q1, 0.f) * w;
    }
    a00 += b2; a01 += b2; a10 += b2; a11 += b2;
    if (mlp == 0) {
        a00 = 1.f / (1.f + __expf(-a00)); a01 = 1.f / (1.f + __expf(-a01));
        a10 = 1.f / (1.f + __expf(-a10)); a11 = 1.f / (1.f + __expf(-a11));
    } else {
        a00 = tanhf(a00) * 0.2f; a01 = tanhf(a01) * 0.2f;
        a10 = tanhf(a10) * 0.2f; a11 = tanhf(a11) * 0.2f;
    }
    Z[(long)(i0 + ty) * NN2 + j0 + tx]           = a00;
    Z[(long)(i0 + ty) * NN2 + j0 + tx + 16]      = a01;
    Z[(long)(i0 + ty + 16) * NN2 + j0 + tx]      = a10;
    Z[(long)(i0 + ty + 16) * NN2 + j0 + tx + 16] = a11;
}

// elementwise physics + per-(b,i) reduction
__global__ void k_phys(const float* __restrict__ ZA, const float* __restrict__ ZB,
                       const float* __restrict__ pos1, const float* __restrict__ pos2,
                       const float* __restrict__ r1, const float* __restrict__ r2,
                       const float* __restrict__ nm1, const float* __restrict__ nm2,
                       const float* __restrict__ A_int, float* __restrict__ part) {
    int b = blockIdx.x >> 7, i = blockIdx.x & 127;
    int t = threadIdx.x;
    float px = pos1[(b * NN1 + i) * 3 + 0];
    float py = pos1[(b * NN1 + i) * 3 + 1];
    float pz = pos1[(b * NN1 + i) * 3 + 2];
    float rr1 = r1[b * NN1 + i];
    float m1  = nm1[b * NN1 + i];
    size_t zbase = (size_t)b * NN1 * NN2 + (size_t)i * NN2;
    size_t abase = (size_t)b * 8 * NN1 * NN2 + (size_t)i * NN2;
    const size_t chw = (size_t)NN1 * NN2;
    float s0 = 0.f, s1 = 0.f, s2 = 0.f, s3 = 0.f;
    for (int j = t; j < NN2; j += 128) {
        float Aw = ZA[zbase + j];
        float Bw = ZB[zbase + j];
        float dx = px - pos2[(b * NN2 + j) * 3 + 0];
        float dy = py - pos2[(b * NN2 + j) * 3 + 1];
        float dz = pz - pos2[(b * NN2 + j) * 3 + 2];
        float dm = sqrtf(dx * dx + dy * dy + dz * dz + 1e-10f);
        if (dm < 0.5f) dm = 1e10f;
        float dm0 = rr1 + r2[b * NN2 + j] + Bw;
        float dm0s = (dm0 < 1e-4f) ? 1.f : dm0;
        float rq = dm0s / dm;
        float rq2 = rq * rq;
        float r6 = rq2 * rq2 * rq2;
        float evdw = fminf(r6 * r6 - 2.f * r6, 100.f);
        float Aamp = Aw * (0.0356f - 0.0178f) + 0.0178f;
        s0 += Aamp * evdw * m1 * nm2[b * NN2 + j];
        float dmd = dm - dm0;
        float a1 = A_int[abase + 1 * chw + j];
        float a7 = A_int[abase + 7 * chw + j];
        float a6 = A_int[abase + 6 * chw + j];
        s1 += fminf(fmaxf(dmd * a1 * (-1.f / 0.7f), 0.f), 1.f);
        s2 += fminf(fmaxf(dmd * a7 * (-1.f / 0.7f), 0.f), 1.f);
        s3 += fminf(fmaxf((1.5f - dmd) * a6, 0.f), 1.f);
    }
    #pragma unroll
    for (int o = 16; o > 0; o >>= 1) {
        s0 += __shfl_down_sync(0xffffffffu, s0, o);
        s1 += __shfl_down_sync(0xffffffffu, s1, o);
        s2 += __shfl_down_sync(0xffffffffu, s2, o);
        s3 += __shfl_down_sync(0xffffffffu, s3, o);
    }
    __shared__ float acc[4][4];
    int lane = t & 31, w = t >> 5;
    if (lane == 0) { acc[w][0] = s0; acc[w][1] = s1; acc[w][2] = s2; acc[w][3] = s3; }
    __syncthreads();
    if (t < 4)
        part[((size_t)b * NN1 + i) * 4 + t] = acc[0][t] + acc[1][t] + acc[2][t] + acc[3][t];
}

__global__ void k_final(const float* __restrict__ part, const float* __restrict__ rotor,
                        const float* __restrict__ duff, const float* __restrict__ hbc,
                        const float* __restrict__ hyc, const float* __restrict__ vdc,
                        const float* __restrict__ rtc, float* __restrict__ out) {
    int b = blockIdx.x, t = threadIdx.x;
    size_t base = ((size_t)b * NN1 + t) * 4;
    float v0 = part[base + 0], v1 = part[base + 1], v2 = part[base + 2], v3 = part[base + 3];
    #pragma unroll
    for (int o = 16; o > 0; o >>= 1) {
        v0 += __shfl_down_sync(0xffffffffu, v0, o);
        v1 += __shfl_down_sync(0xffffffffu, v1, o);
        v2 += __shfl_down_sync(0xffffffffu, v2, o);
        v3 += __shfl_down_sync(0xffffffffu, v3, o);
    }
    __shared__ float red[4][4];
    if ((t & 31) == 0) {
        int w = t >> 5;
        red[w][0] = v0; red[w][1] = v1; red[w][2] = v2; red[w][3] = v3;
    }
    __syncthreads();
    if (t == 0) {
        float s0 = red[0][0] + red[1][0] + red[2][0] + red[3][0];
        float s1 = red[0][1] + red[1][1] + red[2][1] + red[3][1];
        float s2 = red[0][2] + red[1][2] + red[2][2] + red[3][2];
        float s3 = red[0][3] + red[1][3] + red[2][3] + red[3][3];
        float hb = -hbc[0] * hbc[0];
        float hy = -hyc[0] * hyc[0];
        float inv = 1.f / (1.f + rtc[0] * rtc[0] * rotor[b]);
        out[b * 5 + 0] = s0 * inv;
        out[b * 5 + 1] = s1 * hb * inv;
        out[b * 5 + 2] = s2 * hb * inv;
        out[b * 5 + 3] = s3 * hy * inv;
        out[b * 5 + 4] = duff[b] * vdc[0] * vdc[0] * inv;
    }
}

// ---------------- host side ----------------
extern "C" void kernel_launch(void* const* d_in, const int* in_sizes, int n_in,
                              void* d_out, int out_size) {
    (void)in_sizes; (void)n_in; (void)out_size;
    const float* h1      = (const float*)d_in[0];
    const float* adj1    = (const float*)d_in[1];
    const float* h2      = (const float*)d_in[2];
    const float* adj2    = (const float*)d_in[3];
    const float* A_int   = (const float*)d_in[4];
    const float* pos1    = (const float*)d_in[5];
    const float* pos2    = (const float*)d_in[6];
    const float* rotor   = (const float*)d_in[7];
    const float* vdw_r1  = (const float*)d_in[8];
    const float* vdw_r2  = (const float*)d_in[9];
    const float* duff    = (const float*)d_in[10];
    const float* nm1     = (const float*)d_in[11];
    const float* nm2     = (const float*)d_in[12];
    const float* node_W  = (const float*)d_in[13];
    const float* gat_W   = (const float*)d_in[14];
    const float* gat_b   = (const float*)d_in[15];
    const float* gat_A   = (const float*)d_in[16];
    const float* gate_W  = (const float*)d_in[17];
    const float* gate_b  = (const float*)d_in[18];
    const float* vdwA_W1 = (const float*)d_in[19];
    const float* vdwA_b1 = (const float*)d_in[20];
    const float* vdwA_W2 = (const float*)d_in[21];
    const float* vdwA_b2 = (const float*)d_in[22];
    const float* vdwB_W1 = (const float*)d_in[23];
    const float* vdwB_b1 = (const float*)d_in[24];
    const float* vdwB_W2 = (const float*)d_in[25];
    const float* vdwB_b2 = (const float*)d_in[26];
    const float* hbond   = (const float*)d_in[27];
    const float* hydro   = (const float*)d_in[28];
    const float* vdwc    = (const float*)d_in[29];
    const float* rotc    = (const float*)d_in[30];
    float* out = (float*)d_out;

    float *gp, *hp_, *hAp, *e2p, *a2p, *e1p, *a1p, *wap, *bap;
    float *p1a, *p1b, *p2a, *p2b, *zap, *zbp, *partp;
    cudaGetSymbolAddress((void**)&gp,  g_g);
    cudaGetSymbolAddress((void**)&hp_, g_h);
    cudaGetSymbolAddress((void**)&hAp, g_hA);
    cudaGetSymbolAddress((void**)&e2p, g_e2);
    cudaGetSymbolAddress((void**)&a2p, g_a2);
    cudaGetSymbolAddress((void**)&e1p, g_e1);
    cudaGetSymbolAddress((void**)&a1p, g_a1);
    cudaGetSymbolAddress((void**)&wap, g_WA);
    cudaGetSymbolAddress((void**)&bap, g_bA);
    cudaGetSymbolAddress((void**)&p1a, g_P1A);
    cudaGetSymbolAddress((void**)&p1b, g_P1B);
    cudaGetSymbolAddress((void**)&p2a, g_P2A);
    cudaGetSymbolAddress((void**)&p2b, g_P2B);
    cudaGetSymbolAddress((void**)&zap, g_ZA);
    cudaGetSymbolAddress((void**)&zbp, g_ZB);
    cudaGetSymbolAddress((void**)&partp, g_part);

    (void)cudaFuncSetAttribute(k_softmax_both,
                               cudaFuncAttributeMaxDynamicSharedMemorySize,
                               NN2 * 33 * 4);

    // precompute WA, bA; embedding
    k_wa<<<dim3(2, 2, 3), 256>>>(gat_W, gat_A, wap);
    k_bvec<<<3, DD>>>(gat_b, gat_A, bap);
    k_embed_both<<<MROWS, DD>>>(h1, h2, node_W, gp);

    for (int l = 0; l < 3; l++) {
        const float* W  = gat_W  + (size_t)l * DD * DD;
        const float* bW = gat_b  + (size_t)l * DD;
        const float* WA = wap    + (size_t)l * DD * DD;
        const float* bA = bap    + (size_t)l * DD;
        const float* gW = gate_W + (size_t)l * 2 * DD;
        const float* gb = gate_b + l;
        k_dual<<<dim3(4, MROWS / 64, 1), 256>>>(gp, W, bW, WA, bA, hp_, hAp);
        k_nt_both<<<dim3(8, 8, 16), 256>>>(hp_, hAp, e2p, e1p);
        k_softmax_both<<<dim3(16, 16), dim3(32, 8), NN2 * 33 * 4>>>(e2p, adj2, a2p,
                                                                    e1p, adj1, a1p);
        k_relugate<<<dim3(1, 16, 16), 256>>>(a2p, a1p, hp_, gp, gW, gb);
    }

    // pair projections (one launch)
    k_proj<<<dim3(2, 64, 4), 256>>>(gp, vdwA_W1, vdwA_b1, vdwB_W1, vdwB_b1,
                                    p1a, p1b, p2a, p2b);
    // pair bilinear-relu MLP matrices
    k_zmat<<<dim3(16, 4, 16), 256>>>(p1a, p1b, p2a, p2b, vdwA_W2, vdwB_W2,
                                     vdwA_b2, vdwB_b2, zap, zbp);
    // physics + reductions
    k_phys<<<BB * NN1, 128>>>(zap, zbp, pos1, pos2, vdw_r1, vdw_r2, nm1, nm2,
                              A_int, partp);
    k_final<<<BB, 128>>>(partp, rotor, duff, hbond, hydro, vdwc, rotc, out);
}